// round 15
// baseline (speedup 1.0000x reference)
#include <cuda_runtime.h>
#include <cuda_bf16.h>
#include <math.h>
#include <stdint.h>

#define BB 8192
#define GG 256
#define EMBD 128
#define NHEAD 4
#define EVT 65536
#define TMAXN 196608  /* 8192 * 24 (counts in [8,24]) */

// ---------------- scratch (static device globals) ----------------------------
__device__ float g_w[BB * GG];
__device__ float g_ck[BB * GG];
__device__ float g_hn[(size_t)TMAXN * EMBD];
__device__ float g_hc[BB * EMBD];
__device__ float g_xc[BB * EMBD];
__device__ float g_h2[BB * EMBD];
__device__ float g_s1n[(size_t)TMAXN * NHEAD];
__device__ float g_d1c[BB * NHEAD];
__device__ float g_fsn[TMAXN];
__device__ float g_fdn[TMAXN];
__device__ float g_fsc[BB];
__device__ float g_fdc[BB];
__device__ float g_s2[BB];
__device__ float g_d2[BB];
__device__ float g_e2v[EVT];
__device__ float g_vmax[BB];
__device__ float g_vsum[BB];
// bf16 split operands
__device__ __nv_bfloat16 g_nh[(size_t)TMAXN * GG];
__device__ __nv_bfloat16 g_nl[(size_t)TMAXN * GG];
__device__ __nv_bfloat16 g_nadjh[(size_t)TMAXN * GG];
__device__ __nv_bfloat16 g_nadjl[(size_t)TMAXN * GG];
__device__ __nv_bfloat16 g_cadjh[BB * GG];
__device__ __nv_bfloat16 g_cadjl[BB * GG];
__device__ __nv_bfloat16 g_ch[BB * GG];
__device__ __nv_bfloat16 g_cl[BB * GG];
__device__ __nv_bfloat16 g_xch[BB * EMBD];
__device__ __nv_bfloat16 g_xcl[BB * EMBD];
__device__ __nv_bfloat16 g_Bqh[GG * GG];    // Wq_n^T  [n][k]
__device__ __nv_bfloat16 g_Bql[GG * GG];
__device__ __nv_bfloat16 g_B1h[EMBD * GG];  // W1^T    [n][k]
__device__ __nv_bfloat16 g_B1l[EMBD * GG];
__device__ __nv_bfloat16 g_BM1h[GG * GG];   // M1^T    [n][k]
__device__ __nv_bfloat16 g_BM1l[GG * GG];
__device__ __nv_bfloat16 g_BWkh[GG * GG];   // Wk_n^T  [n][k]
__device__ __nv_bfloat16 g_BWkl[GG * GG];
__device__ __nv_bfloat16 g_B2h[EMBD * EMBD];// W2^T    [n][k]
__device__ __nv_bfloat16 g_B2l[EMBD * EMBD];

// ---------------- helpers ----------------------------------------------------
__device__ __forceinline__ float warpsum(float v) {
#pragma unroll
    for (int o = 16; o; o >>= 1) v += __shfl_xor_sync(0xffffffffu, v, o);
    return v;
}
__device__ __forceinline__ float warpmax(float v) {
#pragma unroll
    for (int o = 16; o; o >>= 1) v = fmaxf(v, __shfl_xor_sync(0xffffffffu, v, o));
    return v;
}
__device__ __forceinline__ void atomicMaxFloat(float* addr, float value) {
    if (value >= 0.f) atomicMax((int*)addr, __float_as_int(value));
    else              atomicMin((unsigned int*)addr, __float_as_uint(value));
}
__device__ __forceinline__ float lrelu02(float x) { return x > 0.f ? x : 0.2f * x; }
__device__ __forceinline__ float sigm(float x) {
    return __fdividef(1.f, 1.f + __expf(-x));
}
__device__ __forceinline__ float ftanh(float x) {
    float e = __expf(2.f * x);
    return 1.f - __fdividef(2.f, e + 1.f);
}

__device__ __forceinline__ uint32_t smem_u32(const void* p) {
    uint32_t a;
    asm("{ .reg .u64 t; cvta.to.shared.u64 t, %1; cvt.u32.u64 %0, t; }"
        : "=r"(a) : "l"(p));
    return a;
}
__device__ __forceinline__ void bsplit2(float x, float y, uint32_t& h, uint32_t& l) {
    unsigned short hx = __bfloat16_as_ushort(__float2bfloat16(x));
    unsigned short hy = __bfloat16_as_ushort(__float2bfloat16(y));
    float rx = x - __bfloat162float(__ushort_as_bfloat16(hx));
    float ry = y - __bfloat162float(__ushort_as_bfloat16(hy));
    unsigned short lx = __bfloat16_as_ushort(__float2bfloat16(rx));
    unsigned short ly = __bfloat16_as_ushort(__float2bfloat16(ry));
    h = (uint32_t)hx | ((uint32_t)hy << 16);
    l = (uint32_t)lx | ((uint32_t)ly << 16);
}
__device__ __forceinline__ float bf16lo(uint32_t v) {
    return __bfloat162float(__ushort_as_bfloat16((unsigned short)(v & 0xffffu)));
}
__device__ __forceinline__ float bf16hi(uint32_t v) {
    return __bfloat162float(__ushort_as_bfloat16((unsigned short)(v >> 16)));
}

// ---------------- HMMA primitives --------------------------------------------
__device__ __forceinline__ void ldsm_x4(uint32_t addr, uint32_t& r0, uint32_t& r1,
                                        uint32_t& r2, uint32_t& r3) {
    asm volatile("ldmatrix.sync.aligned.m8n8.x4.shared.b16 {%0,%1,%2,%3}, [%4];"
                 : "=r"(r0), "=r"(r1), "=r"(r2), "=r"(r3) : "r"(addr));
}
__device__ __forceinline__ void mma_bf16(float* c, const uint32_t* a,
                                         uint32_t b0, uint32_t b1) {
    asm("mma.sync.aligned.m16n8k16.row.col.f32.bf16.bf16.f32 "
        "{%0,%1,%2,%3}, {%4,%5,%6,%7}, {%8,%9}, {%0,%1,%2,%3};"
        : "+f"(c[0]), "+f"(c[1]), "+f"(c[2]), "+f"(c[3])
        : "r"(a[0]), "r"(a[1]), "r"(a[2]), "r"(a[3]), "r"(b0), "r"(b1));
}

// cp.async stage: 256 threads, 1 int4/thread, 128 rows x 16 bf16, 48B stride.
__device__ __forceinline__ void stage_async(const __nv_bfloat16* __restrict__ src,
                                            int row0, int M, int k0, int rowElems,
                                            __nv_bfloat16* dst, int tid) {
    int row = tid >> 1, half = tid & 1;
    const void* s = (const uint8_t*)src + (size_t)(row0 + row) * (rowElems * 2) +
                    (size_t)(k0 * 2 + half * 16);
    uint32_t d = smem_u32((uint8_t*)dst + row * 48 + half * 16);
    int sz = (row0 + row < M) ? 16 : 0;
    asm volatile("cp.async.cg.shared.global [%0], [%1], 16, %2;"
                 :: "r"(d), "l"(s), "r"(sz));
}
#define CP_COMMIT() asm volatile("cp.async.commit_group;" ::: "memory")
#define CP_WAIT0()  asm volatile("cp.async.wait_group 0;" ::: "memory")

#define MMA_3PROD(ACC_)                                                        \
    _Pragma("unroll")                                                          \
    for (int rt = 0; rt < 4; rt++)                                             \
        _Pragma("unroll")                                                      \
        for (int cp = 0; cp < 2; cp++) {                                       \
            mma_bf16(ACC_[rt][2 * cp],     aH[rt], bH[cp][0], bH[cp][2]);      \
            mma_bf16(ACC_[rt][2 * cp + 1], aH[rt], bH[cp][1], bH[cp][3]);      \
        }                                                                      \
    _Pragma("unroll")                                                          \
    for (int rt = 0; rt < 4; rt++)                                             \
        _Pragma("unroll")                                                      \
        for (int cp = 0; cp < 2; cp++) {                                       \
            mma_bf16(ACC_[rt][2 * cp],     aH[rt], bL[cp][0], bL[cp][2]);      \
            mma_bf16(ACC_[rt][2 * cp + 1], aH[rt], bL[cp][1], bL[cp][3]);      \
        }                                                                      \
    _Pragma("unroll")                                                          \
    for (int rt = 0; rt < 4; rt++)                                             \
        _Pragma("unroll")                                                      \
        for (int cp = 0; cp < 2; cp++) {                                       \
            mma_bf16(ACC_[rt][2 * cp],     aL[rt], bH[cp][0], bH[cp][2]);      \
            mma_bf16(ACC_[rt][2 * cp + 1], aL[rt], bH[cp][1], bH[cp][3]);      \
        }

#define HMMA_MAINLOOP3(AH_, AL_, BH_, BL_, M_, row0_, col0_, KELA_, KELB_, KSTEPS_) \
    {                                                                          \
        const int lane_ = tid & 31, w_ = tid >> 5;                             \
        const int wr_ = w_ >> 2, wc_ = w_ & 3;                                 \
        const uint32_t aoff_ =                                                 \
            (uint32_t)((wr_ * 64 + (lane_ & 15)) * 48 + (lane_ >> 4) * 16);    \
        const uint32_t boff_ =                                                 \
            (uint32_t)((wc_ * 32 + (lane_ & 15)) * 48 + (lane_ >> 4) * 16);    \
        int buf = 0;                                                           \
        stage_async(AH_, row0_, M_, 0, KELA_, &sA[0][0][0], tid);              \
        stage_async(AL_, row0_, M_, 0, KELA_, &sA[0][1][0], tid);              \
        stage_async(BH_, col0_, 1 << 30, 0, KELB_, &sB[0][0][0], tid);         \
        stage_async(BL_, col0_, 1 << 30, 0, KELB_, &sB[0][1][0], tid);         \
        CP_COMMIT(); CP_WAIT0();                                               \
        __syncthreads();                                                       \
        for (int it = 0; it < (KSTEPS_); it++) {                               \
            if (it + 1 < (KSTEPS_)) {                                          \
                int k0 = (it + 1) * 16;                                        \
                stage_async(AH_, row0_, M_, k0, KELA_, &sA[buf ^ 1][0][0], tid); \
                stage_async(AL_, row0_, M_, k0, KELA_, &sA[buf ^ 1][1][0], tid); \
                stage_async(BH_, col0_, 1 << 30, k0, KELB_, &sB[buf ^ 1][0][0], tid); \
                stage_async(BL_, col0_, 1 << 30, k0, KELB_, &sB[buf ^ 1][1][0], tid); \
                CP_COMMIT();                                                   \
            }                                                                  \
            uint32_t aB0 = smem_u32(&sA[buf][0][0]) + aoff_;                   \
            uint32_t aB1 = smem_u32(&sA[buf][1][0]) + aoff_;                   \
            uint32_t bB0 = smem_u32(&sB[buf][0][0]) + boff_;                   \
            uint32_t bB1 = smem_u32(&sB[buf][1][0]) + boff_;                   \
            uint32_t aH[4][4], aL[4][4], bH[2][4], bL[2][4];                   \
            _Pragma("unroll")                                                  \
            for (int rt = 0; rt < 4; rt++) {                                   \
                ldsm_x4(aB0 + rt * 768, aH[rt][0], aH[rt][1], aH[rt][2], aH[rt][3]); \
                ldsm_x4(aB1 + rt * 768, aL[rt][0], aL[rt][1], aL[rt][2], aL[rt][3]); \
            }                                                                  \
            _Pragma("unroll")                                                  \
            for (int cp = 0; cp < 2; cp++) {                                   \
                ldsm_x4(bB0 + cp * 768, bH[cp][0], bH[cp][1], bH[cp][2], bH[cp][3]); \
                ldsm_x4(bB1 + cp * 768, bL[cp][0], bL[cp][1], bL[cp][2], bL[cp][3]); \
            }                                                                  \
            MMA_3PROD(acc)                                                     \
            if (it + 1 < (KSTEPS_)) CP_WAIT0();                                \
            __syncthreads();                                                   \
            buf ^= 1;                                                          \
        }                                                                      \
    }

#define SMEM_DECL                                                              \
    __shared__ __align__(16) __nv_bfloat16 sA[2][2][128 * 24];                 \
    __shared__ __align__(16) __nv_bfloat16 sB[2][2][128 * 24];

#define EPI_VARS                                                               \
    const int lane = tid & 31, w = tid >> 5, wr = w >> 2, wc = w & 3;          \
    const int g = lane >> 2, q = lane & 3;

// ---------------- merged prep: init + M1 + weight splits + c split ------------
__global__ void prep_all(const float* __restrict__ Wq_c,
                         const float* __restrict__ Wk_c,
                         const float* __restrict__ Wq_n,
                         const float* __restrict__ W1,
                         const float* __restrict__ W2,
                         const float* __restrict__ Wk_n,
                         const float4* __restrict__ cin,
                         float* __restrict__ out_xn) {
    int b = blockIdx.x, tid = threadIdx.x;
    if (b < 256) {
        int p = b, lane = tid & 31, warp = tid >> 5;
        __shared__ float sq[128];
        if (tid < 128) sq[tid] = Wq_c[p * 128 + tid];
        __syncthreads();
        for (int k = warp; k < 256; k += 8) {
            const float* row = Wk_c + (size_t)k * 128;
            float acc = 0.f;
#pragma unroll
            for (int i = 0; i < 4; i++) acc += row[lane + 32 * i] * sq[lane + 32 * i];
            acc = warpsum(acc);
            if (!lane) {
                __nv_bfloat16 h = __float2bfloat16(acc);
                g_BM1h[k * 256 + p] = h;
                g_BM1l[k * 256 + p] = __float2bfloat16(acc - __bfloat162float(h));
            }
        }
    } else if (b < 512) {
        int idx = (b - 256) * 256 + tid, k = idx >> 8, n = idx & 255;
        float x = Wq_n[k * 256 + n];
        __nv_bfloat16 h = __float2bfloat16(x);
        g_Bqh[n * 256 + k] = h;
        g_Bql[n * 256 + k] = __float2bfloat16(x - __bfloat162float(h));
    } else if (b < 640) {
        int idx = (b - 512) * 256 + tid, k = idx >> 7, n = idx & 127;
        float x = W1[k * 128 + n];
        __nv_bfloat16 h = __float2bfloat16(x);
        g_B1h[n * 256 + k] = h;
        g_B1l[n * 256 + k] = __float2bfloat16(x - __bfloat162float(h));
    } else if (b < 704) {
        int idx = (b - 640) * 256 + tid, k = idx >> 7, n = idx & 127;
        float x = W2[k * 128 + n];
        __nv_bfloat16 h = __float2bfloat16(x);
        g_B2h[n * 128 + k] = h;
        g_B2l[n * 128 + k] = __float2bfloat16(x - __bfloat162float(h));
    } else if (b < 960) {
        int idx = (b - 704) * 256 + tid, k = idx >> 8, n = idx & 255;
        float x = Wk_n[k * 256 + n];
        __nv_bfloat16 h = __float2bfloat16(x);
        g_BWkh[n * 256 + k] = h;
        g_BWkl[n * 256 + k] = __float2bfloat16(x - __bfloat162float(h));
    } else if (b < 3008) {
        int i = (b - 960) * 256 + tid;
        float4 v = cin[i];
        uint32_t h0, l0, h1, l1;
        bsplit2(v.x, v.y, h0, l0);
        bsplit2(v.z, v.w, h1, l1);
        ((uint32_t*)g_ch)[i * 2] = h0; ((uint32_t*)g_ch)[i * 2 + 1] = h1;
        ((uint32_t*)g_cl)[i * 2] = l0; ((uint32_t*)g_cl)[i * 2 + 1] = l1;
    } else {
        int i = (b - 3008) * 256 + tid;
        if (i < BB * EMBD) out_xn[i] = 0.f;
        if (i < TMAXN) { g_fsn[i] = 0.f; g_fdn[i] = 0.f; }
        if (i < BB) {
            g_vmax[i] = -1e30f; g_vsum[i] = 0.f;
            g_fsc[i] = 0.f; g_fdc[i] = 0.f;
            g_s2[i] = 0.f;  g_d2[i] = 0.f;
        }
    }
}

// ======== HMMA GEMM: merged w/ck ==============================================
#define WCK_SMEM (12 * 3072 * 2)   /* 73728 B */
__global__ void __launch_bounds__(256) hmma_wck(float* __restrict__ Cw,
                                                float* __restrict__ Cck) {
    extern __shared__ __align__(16) __nv_bfloat16 smem_dyn[];
    __nv_bfloat16* sAp = smem_dyn;
    __nv_bfloat16* sBp = smem_dyn + 4 * 3072;
    const int tid = threadIdx.x;
    const int row0 = blockIdx.y * 128, col0 = blockIdx.x * 128;
    float acc0[4][4][4] = {}, acc1[4][4][4] = {};
    const int lane = tid & 31, w = tid >> 5, wr = w >> 2, wc = w & 3;
    const uint32_t aoff = (uint32_t)((wr * 64 + (lane & 15)) * 48 + (lane >> 4) * 16);
    const uint32_t boff = (uint32_t)((wc * 32 + (lane & 15)) * 48 + (lane >> 4) * 16);
    stage_async(g_ch, row0, BB, 0, 256, sAp, tid);
    stage_async(g_cl, row0, BB, 0, 256, sAp + 3072, tid);
    stage_async(g_BM1h, col0, 1 << 30, 0, 256, sBp, tid);
    stage_async(g_BM1l, col0, 1 << 30, 0, 256, sBp + 3072, tid);
    stage_async(g_BWkh, col0, 1 << 30, 0, 256, sBp + 2 * 3072, tid);
    stage_async(g_BWkl, col0, 1 << 30, 0, 256, sBp + 3 * 3072, tid);
    CP_COMMIT(); CP_WAIT0();
    __syncthreads();
    int buf = 0;
    for (int it = 0; it < 16; it++) {
        if (it + 1 < 16) {
            int k0 = (it + 1) * 16, nb = buf ^ 1;
            stage_async(g_ch, row0, BB, k0, 256, sAp + (nb * 2 + 0) * 3072, tid);
            stage_async(g_cl, row0, BB, k0, 256, sAp + (nb * 2 + 1) * 3072, tid);
            stage_async(g_BM1h, col0, 1 << 30, k0, 256, sBp + (nb * 4 + 0) * 3072, tid);
            stage_async(g_BM1l, col0, 1 << 30, k0, 256, sBp + (nb * 4 + 1) * 3072, tid);
            stage_async(g_BWkh, col0, 1 << 30, k0, 256, sBp + (nb * 4 + 2) * 3072, tid);
            stage_async(g_BWkl, col0, 1 << 30, k0, 256, sBp + (nb * 4 + 3) * 3072, tid);
            CP_COMMIT();
        }
        uint32_t aB0 = smem_u32(sAp + (buf * 2 + 0) * 3072) + aoff;
        uint32_t aB1 = smem_u32(sAp + (buf * 2 + 1) * 3072) + aoff;
        uint32_t aH[4][4], aL[4][4];
#pragma unroll
        for (int rt = 0; rt < 4; rt++) {
            ldsm_x4(aB0 + rt * 768, aH[rt][0], aH[rt][1], aH[rt][2], aH[rt][3]);
            ldsm_x4(aB1 + rt * 768, aL[rt][0], aL[rt][1], aL[rt][2], aL[rt][3]);
        }
        {
            uint32_t bB0 = smem_u32(sBp + (buf * 4 + 0) * 3072) + boff;
            uint32_t bB1 = smem_u32(sBp + (buf * 4 + 1) * 3072) + boff;
            uint32_t bH[2][4], bL[2][4];
#pragma unroll
            for (int cp = 0; cp < 2; cp++) {
                ldsm_x4(bB0 + cp * 768, bH[cp][0], bH[cp][1], bH[cp][2], bH[cp][3]);
                ldsm_x4(bB1 + cp * 768, bL[cp][0], bL[cp][1], bL[cp][2], bL[cp][3]);
            }
            MMA_3PROD(acc0)
        }
        {
            uint32_t bB0 = smem_u32(sBp + (buf * 4 + 2) * 3072) + boff;
            uint32_t bB1 = smem_u32(sBp + (buf * 4 + 3) * 3072) + boff;
            uint32_t bH[2][4], bL[2][4];
#pragma unroll
            for (int cp = 0; cp < 2; cp++) {
                ldsm_x4(bB0 + cp * 768, bH[cp][0], bH[cp][1], bH[cp][2], bH[cp][3]);
                ldsm_x4(bB1 + cp * 768, bL[cp][0], bL[cp][1], bL[cp][2], bL[cp][3]);
            }
            MMA_3PROD(acc1)
        }
        if (it + 1 < 16) CP_WAIT0();
        __syncthreads();
        buf ^= 1;
    }
    const int gg = lane >> 2, q = lane & 3;
#pragma unroll
    for (int rt = 0; rt < 4; rt++)
#pragma unroll
        for (int i = 0; i < 2; i++) {
            int er = row0 + wr * 64 + rt * 16 + gg + i * 8;
#pragma unroll
            for (int ct = 0; ct < 4; ct++) {
                int c = col0 + wc * 32 + ct * 8 + q * 2;
                *(float2*)(Cw + (size_t)er * 256 + c) =
                    make_float2(acc0[rt][ct][i * 2], acc0[rt][ct][i * 2 + 1]);
                *(float2*)(Cck + (size_t)er * 256 + c) =
                    make_float2(acc1[rt][ct][i * 2], acc1[rt][ct][i * 2 + 1]);
            }
        }
}

// ================= HMMA GEMM: gate ============================================
__global__ void __launch_bounds__(256) hmma_gate(
    const float* __restrict__ Afp, const float* __restrict__ ck,
    const int* __restrict__ seg, const int* __restrict__ offs,
    float* __restrict__ out_attn, int M) {
    SMEM_DECL
    const int tid = threadIdx.x;
    const int row0 = blockIdx.y * 128, col0 = blockIdx.x * 128;
    float acc[4][4][4] = {};
    HMMA_MAINLOOP3(g_nh, g_nl, g_Bqh, g_Bql, M, row0, col0, 256, 256, 16);
    EPI_VARS
#pragma unroll
    for (int rt = 0; rt < 4; rt++)
#pragma unroll
        for (int i = 0; i < 2; i++) {
            int er = row0 + wr * 64 + rt * 16 + g + i * 8;
            if (er >= M) continue;
            int sg = seg[er];
            bool first = (offs[sg] == er);
            const float* ckrow = ck + (size_t)sg * 256;
            const float* arow = Afp + (size_t)er * 256;
#pragma unroll
            for (int ct = 0; ct < 4; ct++) {
                int c = col0 + wc * 32 + ct * 8 + q * 2;
                float2 ckv = *(const float2*)(ckrow + c);
                float2 av = *(const float2*)(arow + c);
                float g0 = ftanh(acc[rt][ct][i * 2 + 0] * ckv.x);
                float g1 = ftanh(acc[rt][ct][i * 2 + 1] * ckv.y);
                uint32_t hh, ll;
                bsplit2(av.x * g0, av.y * g1, hh, ll);
                *(uint32_t*)((uint8_t*)g_nadjh + (size_t)er * 512 + c * 2) = hh;
                *(uint32_t*)((uint8_t*)g_nadjl + (size_t)er * 512 + c * 2) = ll;
                if (first)
                    *(float2*)(out_attn + (size_t)sg * 256 + c) = make_float2(g0, g1);
            }
        }
}

// ====== HMMA GEMM: [nadj; cadj] @ W1, fused per-node scalar epilogue ==========
__global__ void __launch_bounds__(256) hmma_w1(
    float* __restrict__ C0, float* __restrict__ C1,
    const float* __restrict__ a_src1, const float* __restrict__ a_dst1,
    const float* __restrict__ a_feat,
    int M0, int M1, int tiles0) {
    SMEM_DECL
    const int tid = threadIdx.x;
    int t = blockIdx.y;
    const __nv_bfloat16 *Ah, *Al;
    float* C; int M, row0;
    bool is_n = (t < tiles0);
    if (is_n) { Ah = g_nadjh; Al = g_nadjl; C = C0; M = M0; row0 = t * 128; }
    else      { Ah = g_cadjh; Al = g_cadjl; C = C1; M = M1; row0 = (t - tiles0) * 128; }
    float acc[4][4][4] = {};
    HMMA_MAINLOOP3(Ah, Al, g_B1h, g_B1l, M, row0, 0, 256, 256, 16);
    EPI_VARS
    float av_[8], af_[8], ag_[8];
    const float* avec = is_n ? a_src1 : a_dst1;
#pragma unroll
    for (int ct = 0; ct < 4; ct++)
#pragma unroll
        for (int j = 0; j < 2; j++) {
            int c = wc * 32 + ct * 8 + q * 2 + j;
            av_[ct * 2 + j] = avec[c];
            af_[ct * 2 + j] = a_feat[c];
            ag_[ct * 2 + j] = a_feat[128 + c];
        }
#pragma unroll
    for (int rt = 0; rt < 4; rt++)
#pragma unroll
        for (int i = 0; i < 2; i++) {
            int er = row0 + wr * 64 + rt * 16 + g + i * 8;
            float s1 = 0.f, fs = 0.f, fd = 0.f;
            bool ok = (er < M);
            if (ok) {
                float* crow = C + (size_t)er * 128;
#pragma unroll
                for (int ct = 0; ct < 4; ct++) {
                    int c = wc * 32 + ct * 8 + q * 2;
                    float v0 = acc[rt][ct][i * 2 + 0], v1 = acc[rt][ct][i * 2 + 1];
                    *(float2*)(crow + c) = make_float2(v0, v1);
                    s1 += v0 * av_[ct * 2] + v1 * av_[ct * 2 + 1];
                    fs += v0 * af_[ct * 2] + v1 * af_[ct * 2 + 1];
                    fd += v0 * ag_[ct * 2] + v1 * ag_[ct * 2 + 1];
                }
            }
            s1 += __shfl_xor_sync(0xffffffffu, s1, 1);
            s1 += __shfl_xor_sync(0xffffffffu, s1, 2);
            fs += __shfl_xor_sync(0xffffffffu, fs, 1);
            fs += __shfl_xor_sync(0xffffffffu, fs, 2);
            fd += __shfl_xor_sync(0xffffffffu, fd, 1);
            fd += __shfl_xor_sync(0xffffffffu, fd, 2);
            if (ok && q == 0) {
                if (is_n) {
                    g_s1n[(size_t)er * 4 + wc] = s1;
                    atomicAdd(&g_fsn[er], fs);
                    atomicAdd(&g_fdn[er], fd);
                } else {
                    g_d1c[er * 4 + wc] = s1;
                    atomicAdd(&g_fsc[er], fs);
                    atomicAdd(&g_fdc[er], fd);
                }
            }
        }
}

// ====== HMMA GEMM: h2 = xc @ W2, fused s2/d2 scalar epilogue ==================
__global__ void __launch_bounds__(256) hmma_h2(
    float* __restrict__ C,
    const float* __restrict__ a_src2, const float* __restrict__ a_dst2) {
    SMEM_DECL
    const int tid = threadIdx.x;
    const int row0 = blockIdx.y * 128;
    float acc[4][4][4] = {};
    HMMA_MAINLOOP3(g_xch, g_xcl, g_B2h, g_B2l, BB, row0, 0, 128, 128, 8);
    EPI_VARS
    float av_[8], ad_[8];
#pragma unroll
    for (int ct = 0; ct < 4; ct++)
#pragma unroll
        for (int j = 0; j < 2; j++) {
            int c = wc * 32 + ct * 8 + q * 2 + j;
            av_[ct * 2 + j] = a_src2[c];
            ad_[ct * 2 + j] = a_dst2[c];
        }
#pragma unroll
    for (int rt = 0; rt < 4; rt++)
#pragma unroll
        for (int i = 0; i < 2; i++) {
            int er = row0 + wr * 64 + rt * 16 + g + i * 8;
            float* crow = C + (size_t)er * 128;
            float s = 0.f, d = 0.f;
#pragma unroll
            for (int ct = 0; ct < 4; ct++) {
                int c = wc * 32 + ct * 8 + q * 2;
                float v0 = acc[rt][ct][i * 2 + 0], v1 = acc[rt][ct][i * 2 + 1];
                *(float2*)(crow + c) = make_float2(v0, v1);
                s += v0 * av_[ct * 2] + v1 * av_[ct * 2 + 1];
                d += v0 * ad_[ct * 2] + v1 * ad_[ct * 2 + 1];
            }
            s += __shfl_xor_sync(0xffffffffu, s, 1);
            s += __shfl_xor_sync(0xffffffffu, s, 2);
            d += __shfl_xor_sync(0xffffffffu, d, 1);
            d += __shfl_xor_sync(0xffffffffu, d, 2);
            if (q == 0) {
                atomicAdd(&g_s2[er], s);
                atomicAdd(&g_d2[er], d);
            }
        }
}

// ---------------- stage A: single-pass via smem row cache ---------------------
__global__ void __launch_bounds__(128) stageA(
    const float* __restrict__ cin, const float* __restrict__ nin,
    const float* __restrict__ counts_f, const int* __restrict__ offs,
    float* __restrict__ out_gate, float* __restrict__ out_nein) {
    int g = blockIdx.x;
    int tid = threadIdx.x, lane = tid & 31, warp = tid >> 5;
    int base = offs[g];
    int cnt = (int)(counts_f[g] + 0.5f);
    __shared__ float s_w[256];
    __shared__ float s_attn[32];
    __shared__ float s_rows[24][256];   // 24KB: all neighbor rows cached
    s_w[tid] = g_w[(size_t)g * 256 + tid];
    s_w[tid + 128] = g_w[(size_t)g * 256 + 128 + tid];
    // single global read pass: cache rows + emit bf16 splits
    for (int idx = tid; idx < cnt * 256; idx += 128) {
        int r = idx >> 8, c = idx & 255;
        size_t go = (size_t)(base + r) * 256 + c;
        float v = nin[go];
        s_rows[r][c] = v;
        __nv_bfloat16 h = __float2bfloat16(v);
        g_nh[go] = h;
        g_nl[go] = __float2bfloat16(v - __bfloat162float(h));
    }
    __syncthreads();
    for (int t = warp; t < cnt; t += 4) {
        float acc = 0.f;
#pragma unroll
        for (int i = 0; i < 8; i++) acc += s_rows[t][lane + 32 * i] * s_w[lane + 32 * i];
        acc = warpsum(acc);
        if (!lane) s_attn[t] = acc * 0.08838834764831845f;
    }
    __syncthreads();
    if (tid == 0) {
        float m = -1e30f;
        for (int t = 0; t < cnt; t++) m = fmaxf(m, s_attn[t]);
        float s = 0.f;
        for (int t = 0; t < cnt; t++) { float e = __expf(s_attn[t] - m); s_attn[t] = e; s += e; }
        float inv = 1.f / (s + 1e-16f);
        for (int t = 0; t < cnt; t++) s_attn[t] *= inv;
    }
    __syncthreads();
    float acc0 = 0.f, acc1 = 0.f, sum0 = 0.f, sum1 = 0.f;
    for (int t = 0; t < cnt; t++) {
        float v0 = s_rows[t][tid], v1 = s_rows[t][tid + 128];
        float a = s_attn[t];
        acc0 += a * v0; acc1 += a * v1;
        sum0 += v0;     sum1 += v1;
    }
    float gate0 = ftanh(acc0), gate1 = ftanh(acc1);
    size_t o = (size_t)g * 256 + tid;
    float c0 = cin[o], c1 = cin[o + 128];
    out_gate[o] = gate0;            out_gate[o + 128] = gate1;
    float ca0 = c0 * gate0, ca1 = c1 * gate1;
    __nv_bfloat16 h0 = __float2bfloat16(ca0);
    __nv_bfloat16 h1 = __float2bfloat16(ca1);
    g_cadjh[o] = h0;                g_cadjh[o + 128] = h1;
    g_cadjl[o] = __float2bfloat16(ca0 - __bfloat162float(h0));
    g_cadjl[o + 128] = __float2bfloat16(ca1 - __bfloat162float(h1));
    out_nein[o] = c0 + sum0;        out_nein[o + 128] = c1 + sum1;
}

// ---------------- GAT1 + fused segmean ----------------------------------------
__global__ void __launch_bounds__(128) gat1(
    const float* __restrict__ counts_f, const int* __restrict__ offs,
    const int* __restrict__ edges, int T, float* __restrict__ out_ew,
    float* __restrict__ out_ne) {
    int g = blockIdx.x;
    int tid = threadIdx.x, lane = tid & 31, warp = tid >> 5;
    int base = offs[g];
    int cnt = (int)(counts_f[g] + 0.5f);
    int E2 = 2 * T;
    __shared__ float s_alpha[32][4];
    int head = warp;
    float d1 = g_d1c[g * 4 + head];
    float m = -1e30f;
    for (int t = lane; t < cnt; t += 32) {
        float e = lrelu02(g_s1n[(size_t)(base + t) * 4 + head] + d1);
        s_alpha[t][head] = e;
        m = fmaxf(m, e);
    }
    m = warpmax(m);
    float ssum = 0.f;
    for (int t = lane; t < cnt; t += 32) {
        float ex = __expf(s_alpha[t][head] - m);
        s_alpha[t][head] = ex;
        ssum += ex;
    }
    ssum = warpsum(ssum);
    float inv = 1.f / (ssum + 1e-16f);
    for (int t = lane; t < cnt; t += 32) s_alpha[t][head] *= inv;
    __syncthreads();
    // fused segmean: cols 2*tid, 2*tid+1 over nadj splits
    {
        float invc = 1.f / counts_f[g];
        float s0 = 0.f, s1 = 0.f;
        for (int t = 0; t < cnt; t++) {
            const uint32_t* ph = (const uint32_t*)(g_nadjh + (size_t)(base + t) * 256);
            const uint32_t* pl = (const uint32_t*)(g_nadjl + (size_t)(base + t) * 256);
            uint32_t hv = ph[tid], lv = pl[tid];
            s0 += bf16lo(hv) + bf16lo(lv);
            s1 += bf16hi(hv) + bf16hi(lv);
        }
        out_ne[(size_t)g * 256 + 2 * tid]     = s0 * invc;
        out_ne[(size_t)g * 256 + 2 * tid + 1] = s1 * invc;
    }
    int h4 = tid >> 5;
    float acc = 0.f;
    for (int t = 0; t < cnt; t++)
        acc += s_alpha[t][h4] * g_hn[(size_t)(base + t) * 128 + tid];
    size_t xo = (size_t)g * 128 + tid;
    g_xc[xo] = acc;
    __nv_bfloat16 xh = __float2bfloat16(acc);
    g_xch[xo] = xh;
    g_xcl[xo] = __float2bfloat16(acc - __bfloat162float(xh));
    if (tid < cnt) {
        int t = tid;
        int ei = base + t;
        float am = 0.25f * (s_alpha[t][0] + s_alpha[t][1] + s_alpha[t][2] + s_alpha[t][3]);
        float a2 = sigm(g_fsn[ei] + g_fdc[g]);
        float4 r1 = make_float4((float)edges[ei], (float)edges[E2 + ei], am, a2);
        *(float4*)(out_ew + (size_t)ei * 4) = r1;
        int ej = T + ei;
        float a2b = sigm(g_fsc[g] + g_fdn[ei]);
        float4 r2 = make_float4((float)edges[ej], (float)edges[E2 + ej], 1.0f, a2b);
        *(float4*)(out_ew + (size_t)ej * 4) = r2;
    }
}

// ---------------- VT graph softmax ----------------------------------------------
__global__ void vt_pass1(const int* __restrict__ evt) {
    int i = blockIdx.x * blockDim.x + threadIdx.x;
    if (i >= EVT) return;
    int sv = evt[i], dv = evt[EVT + i];
    float e = lrelu02(g_s2[sv] + g_d2[dv]);
    g_e2v[i] = e;
    atomicMaxFloat(&g_vmax[dv], e);
}
__global__ void vt_pass2(const int* __restrict__ evt) {
    int i = blockIdx.x * blockDim.x + threadIdx.x;
    if (i >= EVT) return;
    int dv = evt[EVT + i];
    float ex = __expf(g_e2v[i] - g_vmax[dv]);
    g_e2v[i] = ex;
    atomicAdd(&g_vsum[dv], ex);
}
__global__ void __launch_bounds__(128) vt_pass3(const int* __restrict__ evt,
                                                float* __restrict__ out_alpha,
                                                float* __restrict__ out_xn) {
    int i = blockIdx.x;
    int sv = evt[i], dv = evt[EVT + i];
    float alpha = g_e2v[i] / (g_vsum[dv] + 1e-16f);
    if (threadIdx.x == 0) out_alpha[i] = alpha;
    atomicAdd(&out_xn[(size_t)dv * 128 + threadIdx.x],
              alpha * g_h2[(size_t)sv * 128 + threadIdx.x]);
}

// ---------------- host launcher --------------------------------------------------
extern "C" void kernel_launch(void* const* d_in, const int* in_sizes, int n_in,
                              void* d_out, int out_size) {
    const float* c_in    = (const float*)d_in[0];
    const float* nb_in   = (const float*)d_in[1];
    const float* counts  = (const float*)d_in[2];
    const float* Wq_c    = (const float*)d_in[3];
    const float* Wk_c    = (const float*)d_in[4];
    const float* Wq_n    = (const float*)d_in[5];
    const float* Wk_n    = (const float*)d_in[6];
    const float* W1      = (const float*)d_in[7];
    const float* a_src1  = (const float*)d_in[8];
    const float* a_dst1  = (const float*)d_in[9];
    const float* a_feat  = (const float*)d_in[10];
    const float* W2      = (const float*)d_in[11];
    const float* a_src2  = (const float*)d_in[12];
    const float* a_dst2  = (const float*)d_in[13];
    const int*   seg     = (const int*)d_in[14];
    const int*   offs    = (const int*)d_in[17];
    const int*   edges   = (const int*)d_in[18];
    const int*   evt     = (const int*)d_in[19];
    int T = in_sizes[1] / GG;

    float* out = (float*)d_out;
    float* out_xn   = out;
    float* out_gate = out_xn + (size_t)BB * EMBD;
    float* out_attn = out_gate + (size_t)BB * GG;
    float* out_ne   = out_attn + (size_t)BB * GG;
    float* out_nein = out_ne + (size_t)BB * GG;
    float* out_ew   = out_nein + (size_t)BB * GG;
    float* out_avt  = out_ew + (size_t)8 * T;

    float *p_w, *p_ck, *p_hn, *p_hc, *p_h2;
    cudaGetSymbolAddress((void**)&p_w, g_w);
    cudaGetSymbolAddress((void**)&p_ck, g_ck);
    cudaGetSymbolAddress((void**)&p_hn, g_hn);
    cudaGetSymbolAddress((void**)&p_hc, g_hc);
    cudaGetSymbolAddress((void**)&p_h2, g_h2);

    static bool attr_done = false;
    if (!attr_done) {
        cudaFuncSetAttribute(hmma_wck, cudaFuncAttributeMaxDynamicSharedMemorySize, WCK_SMEM);
        attr_done = true;
    }

    int tilesT = (T + 127) / 128;

    prep_all<<<3008 + 4096, 256>>>(Wq_c, Wk_c, Wq_n, W1, W2, Wk_n,
                                   (const float4*)c_in, out_xn);

    hmma_wck<<<dim3(2, BB / 128), 256, WCK_SMEM>>>(p_w, p_ck);

    stageA<<<BB, 128>>>(c_in, nb_in, counts, offs, out_gate, out_nein);

    hmma_gate<<<dim3(2, tilesT), 256>>>(nb_in, p_ck, seg, offs, out_attn, T);

    hmma_w1<<<dim3(1, tilesT + BB / 128), 256>>>(p_hn, p_hc, a_src1, a_dst1,
                                                 a_feat, T, BB, tilesT);

    gat1<<<BB, 128>>>(counts, offs, edges, T, out_ew, out_ne);

    hmma_h2<<<dim3(1, BB / 128), 256>>>(p_h2, a_src2, a_dst2);

    vt_pass1<<<(EVT + 255) / 256, 256>>>(evt);
    vt_pass2<<<(EVT + 255) / 256, 256>>>(evt);
    vt_pass3<<<EVT, 128>>>(evt, out_avt, out_xn);
}

// round 16
// speedup vs baseline: 1.0583x; 1.0583x over previous
#include <cuda_runtime.h>
#include <cuda_bf16.h>
#include <math.h>
#include <stdint.h>

#define BB 8192
#define GG 256
#define EMBD 128
#define NHEAD 4
#define EVT 65536
#define TMAXN 196608  /* 8192 * 24 (counts in [8,24]) */

// ---------------- scratch (static device globals) ----------------------------
__device__ float g_w[BB * GG];
__device__ float g_ck[BB * GG];
__device__ float g_hn[(size_t)TMAXN * EMBD];
__device__ float g_hc[BB * EMBD];
__device__ float g_xc[BB * EMBD];
__device__ float g_h2[BB * EMBD];
__device__ float g_s1n[(size_t)TMAXN * NHEAD];
__device__ float g_d1c[BB * NHEAD];
__device__ float g_fsn[TMAXN];
__device__ float g_fdn[TMAXN];
__device__ float g_fsc[BB];
__device__ float g_fdc[BB];
__device__ float g_s2[BB];
__device__ float g_d2[BB];
__device__ float g_e2v[EVT];
__device__ float g_vmax[BB];
__device__ float g_vsum[BB];
// bf16 split operands
__device__ __nv_bfloat16 g_nh[(size_t)TMAXN * GG];
__device__ __nv_bfloat16 g_nl[(size_t)TMAXN * GG];
__device__ __nv_bfloat16 g_nadjh[(size_t)TMAXN * GG];
__device__ __nv_bfloat16 g_nadjl[(size_t)TMAXN * GG];
__device__ __nv_bfloat16 g_cadjh[BB * GG];
__device__ __nv_bfloat16 g_cadjl[BB * GG];
__device__ __nv_bfloat16 g_ch[BB * GG];
__device__ __nv_bfloat16 g_cl[BB * GG];
__device__ __nv_bfloat16 g_xch[BB * EMBD];
__device__ __nv_bfloat16 g_xcl[BB * EMBD];
__device__ __nv_bfloat16 g_Bqh[GG * GG];    // Wq_n^T  [n][k]
__device__ __nv_bfloat16 g_Bql[GG * GG];
__device__ __nv_bfloat16 g_B1h[EMBD * GG];  // W1^T    [n][k]
__device__ __nv_bfloat16 g_B1l[EMBD * GG];
__device__ __nv_bfloat16 g_BM1h[GG * GG];   // M1^T    [n][k]
__device__ __nv_bfloat16 g_BM1l[GG * GG];
__device__ __nv_bfloat16 g_BWkh[GG * GG];   // Wk_n^T  [n][k]
__device__ __nv_bfloat16 g_BWkl[GG * GG];
__device__ __nv_bfloat16 g_B2h[EMBD * EMBD];// W2^T    [n][k]
__device__ __nv_bfloat16 g_B2l[EMBD * EMBD];

// ---------------- helpers ----------------------------------------------------
__device__ __forceinline__ float warpsum(float v) {
#pragma unroll
    for (int o = 16; o; o >>= 1) v += __shfl_xor_sync(0xffffffffu, v, o);
    return v;
}
__device__ __forceinline__ float warpmax(float v) {
#pragma unroll
    for (int o = 16; o; o >>= 1) v = fmaxf(v, __shfl_xor_sync(0xffffffffu, v, o));
    return v;
}
__device__ __forceinline__ void atomicMaxFloat(float* addr, float value) {
    if (value >= 0.f) atomicMax((int*)addr, __float_as_int(value));
    else              atomicMin((unsigned int*)addr, __float_as_uint(value));
}
__device__ __forceinline__ float lrelu02(float x) { return x > 0.f ? x : 0.2f * x; }
__device__ __forceinline__ float sigm(float x) {
    return __fdividef(1.f, 1.f + __expf(-x));
}
__device__ __forceinline__ float ftanh(float x) {
    float e = __expf(2.f * x);
    return 1.f - __fdividef(2.f, e + 1.f);
}

__device__ __forceinline__ uint32_t smem_u32(const void* p) {
    uint32_t a;
    asm("{ .reg .u64 t; cvta.to.shared.u64 t, %1; cvt.u32.u64 %0, t; }"
        : "=r"(a) : "l"(p));
    return a;
}
__device__ __forceinline__ void bsplit2(float x, float y, uint32_t& h, uint32_t& l) {
    unsigned short hx = __bfloat16_as_ushort(__float2bfloat16(x));
    unsigned short hy = __bfloat16_as_ushort(__float2bfloat16(y));
    float rx = x - __bfloat162float(__ushort_as_bfloat16(hx));
    float ry = y - __bfloat162float(__ushort_as_bfloat16(hy));
    unsigned short lx = __bfloat16_as_ushort(__float2bfloat16(rx));
    unsigned short ly = __bfloat16_as_ushort(__float2bfloat16(ry));
    h = (uint32_t)hx | ((uint32_t)hy << 16);
    l = (uint32_t)lx | ((uint32_t)ly << 16);
}
__device__ __forceinline__ float bf16lo(uint32_t v) {
    return __bfloat162float(__ushort_as_bfloat16((unsigned short)(v & 0xffffu)));
}
__device__ __forceinline__ float bf16hi(uint32_t v) {
    return __bfloat162float(__ushort_as_bfloat16((unsigned short)(v >> 16)));
}

// ---------------- HMMA primitives --------------------------------------------
__device__ __forceinline__ void ldsm_x4(uint32_t addr, uint32_t& r0, uint32_t& r1,
                                        uint32_t& r2, uint32_t& r3) {
    asm volatile("ldmatrix.sync.aligned.m8n8.x4.shared.b16 {%0,%1,%2,%3}, [%4];"
                 : "=r"(r0), "=r"(r1), "=r"(r2), "=r"(r3) : "r"(addr));
}
__device__ __forceinline__ void mma_bf16(float* c, const uint32_t* a,
                                         uint32_t b0, uint32_t b1) {
    asm volatile(
        "mma.sync.aligned.m16n8k16.row.col.f32.bf16.bf16.f32 "
        "{%0,%1,%2,%3}, {%4,%5,%6,%7}, {%8,%9}, {%0,%1,%2,%3};"
        : "+f"(c[0]), "+f"(c[1]), "+f"(c[2]), "+f"(c[3])
        : "r"(a[0]), "r"(a[1]), "r"(a[2]), "r"(a[3]), "r"(b0), "r"(b1));
}

// cp.async stage: 256 threads, 1 int4/thread, 128 rows x 16 bf16, 48B stride.
__device__ __forceinline__ void stage_async(const __nv_bfloat16* __restrict__ src,
                                            int row0, int M, int k0, int rowElems,
                                            __nv_bfloat16* dst, int tid) {
    int row = tid >> 1, half = tid & 1;
    const void* s = (const uint8_t*)src + (size_t)(row0 + row) * (rowElems * 2) +
                    (size_t)(k0 * 2 + half * 16);
    uint32_t d = smem_u32((uint8_t*)dst + row * 48 + half * 16);
    int sz = (row0 + row < M) ? 16 : 0;
    asm volatile("cp.async.cg.shared.global [%0], [%1], 16, %2;"
                 :: "r"(d), "l"(s), "r"(sz));
}
#define CP_COMMIT() asm volatile("cp.async.commit_group;" ::: "memory")
#define CP_WAIT0()  asm volatile("cp.async.wait_group 0;" ::: "memory")

// R13 interleaved 3-product MMA block (the 557.1-measured schedule)
#define MMA_3PROD(ACC_)                                                        \
    _Pragma("unroll")                                                          \
    for (int rt = 0; rt < 4; rt++)                                             \
        _Pragma("unroll")                                                      \
        for (int cp = 0; cp < 2; cp++) {                                       \
            mma_bf16(ACC_[rt][2 * cp],     aH[rt], bH[cp][0], bH[cp][2]);      \
            mma_bf16(ACC_[rt][2 * cp + 1], aH[rt], bH[cp][1], bH[cp][3]);      \
            mma_bf16(ACC_[rt][2 * cp],     aH[rt], bL[cp][0], bL[cp][2]);      \
            mma_bf16(ACC_[rt][2 * cp + 1], aH[rt], bL[cp][1], bL[cp][3]);      \
            mma_bf16(ACC_[rt][2 * cp],     aL[rt], bH[cp][0], bH[cp][2]);      \
            mma_bf16(ACC_[rt][2 * cp + 1], aL[rt], bH[cp][1], bH[cp][3]);      \
        }

#define HMMA_MAINLOOP3(AH_, AL_, BH_, BL_, M_, row0_, col0_, KELA_, KELB_, KSTEPS_) \
    {                                                                          \
        const int lane_ = tid & 31, w_ = tid >> 5;                             \
        const int wr_ = w_ >> 2, wc_ = w_ & 3;                                 \
        const uint32_t aoff_ =                                                 \
            (uint32_t)((wr_ * 64 + (lane_ & 15)) * 48 + (lane_ >> 4) * 16);    \
        const uint32_t boff_ =                                                 \
            (uint32_t)((wc_ * 32 + (lane_ & 15)) * 48 + (lane_ >> 4) * 16);    \
        int buf = 0;                                                           \
        stage_async(AH_, row0_, M_, 0, KELA_, &sA[0][0][0], tid);              \
        stage_async(AL_, row0_, M_, 0, KELA_, &sA[0][1][0], tid);              \
        stage_async(BH_, col0_, 1 << 30, 0, KELB_, &sB[0][0][0], tid);         \
        stage_async(BL_, col0_, 1 << 30, 0, KELB_, &sB[0][1][0], tid);         \
        CP_COMMIT(); CP_WAIT0();                                               \
        __syncthreads();                                                       \
        for (int it = 0; it < (KSTEPS_); it++) {                               \
            if (it + 1 < (KSTEPS_)) {                                          \
                int k0 = (it + 1) * 16;                                        \
                stage_async(AH_, row0_, M_, k0, KELA_, &sA[buf ^ 1][0][0], tid); \
                stage_async(AL_, row0_, M_, k0, KELA_, &sA[buf ^ 1][1][0], tid); \
                stage_async(BH_, col0_, 1 << 30, k0, KELB_, &sB[buf ^ 1][0][0], tid); \
                stage_async(BL_, col0_, 1 << 30, k0, KELB_, &sB[buf ^ 1][1][0], tid); \
                CP_COMMIT();                                                   \
            }                                                                  \
            uint32_t aB0 = smem_u32(&sA[buf][0][0]) + aoff_;                   \
            uint32_t aB1 = smem_u32(&sA[buf][1][0]) + aoff_;                   \
            uint32_t bB0 = smem_u32(&sB[buf][0][0]) + boff_;                   \
            uint32_t bB1 = smem_u32(&sB[buf][1][0]) + boff_;                   \
            uint32_t aH[4][4], aL[4][4], bH[2][4], bL[2][4];                   \
            _Pragma("unroll")                                                  \
            for (int rt = 0; rt < 4; rt++) {                                   \
                ldsm_x4(aB0 + rt * 768, aH[rt][0], aH[rt][1], aH[rt][2], aH[rt][3]); \
                ldsm_x4(aB1 + rt * 768, aL[rt][0], aL[rt][1], aL[rt][2], aL[rt][3]); \
            }                                                                  \
            _Pragma("unroll")                                                  \
            for (int cp = 0; cp < 2; cp++) {                                   \
                ldsm_x4(bB0 + cp * 768, bH[cp][0], bH[cp][1], bH[cp][2], bH[cp][3]); \
                ldsm_x4(bB1 + cp * 768, bL[cp][0], bL[cp][1], bL[cp][2], bL[cp][3]); \
            }                                                                  \
            MMA_3PROD(acc)                                                     \
            if (it + 1 < (KSTEPS_)) CP_WAIT0();                                \
            __syncthreads();                                                   \
            buf ^= 1;                                                          \
        }                                                                      \
    }

#define SMEM_DECL                                                              \
    __shared__ __align__(16) __nv_bfloat16 sA[2][2][128 * 24];                 \
    __shared__ __align__(16) __nv_bfloat16 sB[2][2][128 * 24];

#define EPI_VARS                                                               \
    const int lane = tid & 31, w = tid >> 5, wr = w >> 2, wc = w & 3;          \
    const int g = lane >> 2, q = lane & 3;

// ---------------- merged prep: init + M1 + weight splits + c split ------------
__global__ void prep_all(const float* __restrict__ Wq_c,
                         const float* __restrict__ Wk_c,
                         const float* __restrict__ Wq_n,
                         const float* __restrict__ W1,
                         const float* __restrict__ W2,
                         const float* __restrict__ Wk_n,
                         const float4* __restrict__ cin,
                         float* __restrict__ out_xn) {
    int b = blockIdx.x, tid = threadIdx.x;
    if (b < 256) {
        int p = b, lane = tid & 31, warp = tid >> 5;
        __shared__ float sq[128];
        if (tid < 128) sq[tid] = Wq_c[p * 128 + tid];
        __syncthreads();
        for (int k = warp; k < 256; k += 8) {
            const float* row = Wk_c + (size_t)k * 128;
            float acc = 0.f;
#pragma unroll
            for (int i = 0; i < 4; i++) acc += row[lane + 32 * i] * sq[lane + 32 * i];
            acc = warpsum(acc);
            if (!lane) {
                __nv_bfloat16 h = __float2bfloat16(acc);
                g_BM1h[k * 256 + p] = h;
                g_BM1l[k * 256 + p] = __float2bfloat16(acc - __bfloat162float(h));
            }
        }
    } else if (b < 512) {
        int idx = (b - 256) * 256 + tid, k = idx >> 8, n = idx & 255;
        float x = Wq_n[k * 256 + n];
        __nv_bfloat16 h = __float2bfloat16(x);
        g_Bqh[n * 256 + k] = h;
        g_Bql[n * 256 + k] = __float2bfloat16(x - __bfloat162float(h));
    } else if (b < 640) {
        int idx = (b - 512) * 256 + tid, k = idx >> 7, n = idx & 127;
        float x = W1[k * 128 + n];
        __nv_bfloat16 h = __float2bfloat16(x);
        g_B1h[n * 256 + k] = h;
        g_B1l[n * 256 + k] = __float2bfloat16(x - __bfloat162float(h));
    } else if (b < 704) {
        int idx = (b - 640) * 256 + tid, k = idx >> 7, n = idx & 127;
        float x = W2[k * 128 + n];
        __nv_bfloat16 h = __float2bfloat16(x);
        g_B2h[n * 128 + k] = h;
        g_B2l[n * 128 + k] = __float2bfloat16(x - __bfloat162float(h));
    } else if (b < 960) {
        int idx = (b - 704) * 256 + tid, k = idx >> 8, n = idx & 255;
        float x = Wk_n[k * 256 + n];
        __nv_bfloat16 h = __float2bfloat16(x);
        g_BWkh[n * 256 + k] = h;
        g_BWkl[n * 256 + k] = __float2bfloat16(x - __bfloat162float(h));
    } else if (b < 3008) {
        int i = (b - 960) * 256 + tid;
        float4 v = cin[i];
        uint32_t h0, l0, h1, l1;
        bsplit2(v.x, v.y, h0, l0);
        bsplit2(v.z, v.w, h1, l1);
        ((uint32_t*)g_ch)[i * 2] = h0; ((uint32_t*)g_ch)[i * 2 + 1] = h1;
        ((uint32_t*)g_cl)[i * 2] = l0; ((uint32_t*)g_cl)[i * 2 + 1] = l1;
    } else {
        int i = (b - 3008) * 256 + tid;
        if (i < BB * EMBD) out_xn[i] = 0.f;
        if (i < TMAXN) { g_fsn[i] = 0.f; g_fdn[i] = 0.f; }
        if (i < BB) {
            g_vmax[i] = -1e30f; g_vsum[i] = 0.f;
            g_fsc[i] = 0.f; g_fdc[i] = 0.f;
            g_s2[i] = 0.f;  g_d2[i] = 0.f;
        }
    }
}

// ======== HMMA GEMM: merged w/ck ==============================================
#define WCK_SMEM (12 * 3072 * 2)   /* 73728 B */
__global__ void __launch_bounds__(256) hmma_wck(float* __restrict__ Cw,
                                                float* __restrict__ Cck) {
    extern __shared__ __align__(16) __nv_bfloat16 smem_dyn[];
    __nv_bfloat16* sAp = smem_dyn;
    __nv_bfloat16* sBp = smem_dyn + 4 * 3072;
    const int tid = threadIdx.x;
    const int row0 = blockIdx.y * 128, col0 = blockIdx.x * 128;
    float acc0[4][4][4] = {}, acc1[4][4][4] = {};
    const int lane = tid & 31, w = tid >> 5, wr = w >> 2, wc = w & 3;
    const uint32_t aoff = (uint32_t)((wr * 64 + (lane & 15)) * 48 + (lane >> 4) * 16);
    const uint32_t boff = (uint32_t)((wc * 32 + (lane & 15)) * 48 + (lane >> 4) * 16);
    stage_async(g_ch, row0, BB, 0, 256, sAp, tid);
    stage_async(g_cl, row0, BB, 0, 256, sAp + 3072, tid);
    stage_async(g_BM1h, col0, 1 << 30, 0, 256, sBp, tid);
    stage_async(g_BM1l, col0, 1 << 30, 0, 256, sBp + 3072, tid);
    stage_async(g_BWkh, col0, 1 << 30, 0, 256, sBp + 2 * 3072, tid);
    stage_async(g_BWkl, col0, 1 << 30, 0, 256, sBp + 3 * 3072, tid);
    CP_COMMIT(); CP_WAIT0();
    __syncthreads();
    int buf = 0;
    for (int it = 0; it < 16; it++) {
        if (it + 1 < 16) {
            int k0 = (it + 1) * 16, nb = buf ^ 1;
            stage_async(g_ch, row0, BB, k0, 256, sAp + (nb * 2 + 0) * 3072, tid);
            stage_async(g_cl, row0, BB, k0, 256, sAp + (nb * 2 + 1) * 3072, tid);
            stage_async(g_BM1h, col0, 1 << 30, k0, 256, sBp + (nb * 4 + 0) * 3072, tid);
            stage_async(g_BM1l, col0, 1 << 30, k0, 256, sBp + (nb * 4 + 1) * 3072, tid);
            stage_async(g_BWkh, col0, 1 << 30, k0, 256, sBp + (nb * 4 + 2) * 3072, tid);
            stage_async(g_BWkl, col0, 1 << 30, k0, 256, sBp + (nb * 4 + 3) * 3072, tid);
            CP_COMMIT();
        }
        uint32_t aB0 = smem_u32(sAp + (buf * 2 + 0) * 3072) + aoff;
        uint32_t aB1 = smem_u32(sAp + (buf * 2 + 1) * 3072) + aoff;
        uint32_t aH[4][4], aL[4][4];
#pragma unroll
        for (int rt = 0; rt < 4; rt++) {
            ldsm_x4(aB0 + rt * 768, aH[rt][0], aH[rt][1], aH[rt][2], aH[rt][3]);
            ldsm_x4(aB1 + rt * 768, aL[rt][0], aL[rt][1], aL[rt][2], aL[rt][3]);
        }
        {
            uint32_t bB0 = smem_u32(sBp + (buf * 4 + 0) * 3072) + boff;
            uint32_t bB1 = smem_u32(sBp + (buf * 4 + 1) * 3072) + boff;
            uint32_t bH[2][4], bL[2][4];
#pragma unroll
            for (int cp = 0; cp < 2; cp++) {
                ldsm_x4(bB0 + cp * 768, bH[cp][0], bH[cp][1], bH[cp][2], bH[cp][3]);
                ldsm_x4(bB1 + cp * 768, bL[cp][0], bL[cp][1], bL[cp][2], bL[cp][3]);
            }
            MMA_3PROD(acc0)
        }
        {
            uint32_t bB0 = smem_u32(sBp + (buf * 4 + 2) * 3072) + boff;
            uint32_t bB1 = smem_u32(sBp + (buf * 4 + 3) * 3072) + boff;
            uint32_t bH[2][4], bL[2][4];
#pragma unroll
            for (int cp = 0; cp < 2; cp++) {
                ldsm_x4(bB0 + cp * 768, bH[cp][0], bH[cp][1], bH[cp][2], bH[cp][3]);
                ldsm_x4(bB1 + cp * 768, bL[cp][0], bL[cp][1], bL[cp][2], bL[cp][3]);
            }
            MMA_3PROD(acc1)
        }
        if (it + 1 < 16) CP_WAIT0();
        __syncthreads();
        buf ^= 1;
    }
    const int gg = lane >> 2, q = lane & 3;
#pragma unroll
    for (int rt = 0; rt < 4; rt++)
#pragma unroll
        for (int i = 0; i < 2; i++) {
            int er = row0 + wr * 64 + rt * 16 + gg + i * 8;
#pragma unroll
            for (int ct = 0; ct < 4; ct++) {
                int c = col0 + wc * 32 + ct * 8 + q * 2;
                *(float2*)(Cw + (size_t)er * 256 + c) =
                    make_float2(acc0[rt][ct][i * 2], acc0[rt][ct][i * 2 + 1]);
                *(float2*)(Cck + (size_t)er * 256 + c) =
                    make_float2(acc1[rt][ct][i * 2], acc1[rt][ct][i * 2 + 1]);
            }
        }
}

// ================= HMMA GEMM: gate ============================================
__global__ void __launch_bounds__(256) hmma_gate(
    const float* __restrict__ Afp, const float* __restrict__ ck,
    const int* __restrict__ seg, const int* __restrict__ offs,
    float* __restrict__ out_attn, int M) {
    SMEM_DECL
    const int tid = threadIdx.x;
    const int row0 = blockIdx.y * 128, col0 = blockIdx.x * 128;
    float acc[4][4][4] = {};
    HMMA_MAINLOOP3(g_nh, g_nl, g_Bqh, g_Bql, M, row0, col0, 256, 256, 16);
    EPI_VARS
#pragma unroll
    for (int rt = 0; rt < 4; rt++)
#pragma unroll
        for (int i = 0; i < 2; i++) {
            int er = row0 + wr * 64 + rt * 16 + g + i * 8;
            if (er >= M) continue;
            int sg = seg[er];
            bool first = (offs[sg] == er);
            const float* ckrow = ck + (size_t)sg * 256;
            const float* arow = Afp + (size_t)er * 256;
#pragma unroll
            for (int ct = 0; ct < 4; ct++) {
                int c = col0 + wc * 32 + ct * 8 + q * 2;
                float2 ckv = *(const float2*)(ckrow + c);
                float2 av = *(const float2*)(arow + c);
                float g0 = ftanh(acc[rt][ct][i * 2 + 0] * ckv.x);
                float g1 = ftanh(acc[rt][ct][i * 2 + 1] * ckv.y);
                uint32_t hh, ll;
                bsplit2(av.x * g0, av.y * g1, hh, ll);
                *(uint32_t*)((uint8_t*)g_nadjh + (size_t)er * 512 + c * 2) = hh;
                *(uint32_t*)((uint8_t*)g_nadjl + (size_t)er * 512 + c * 2) = ll;
                if (first)
                    *(float2*)(out_attn + (size_t)sg * 256 + c) = make_float2(g0, g1);
            }
        }
}

// ====== HMMA GEMM: [nadj; cadj] @ W1, fused per-node scalar epilogue ==========
__global__ void __launch_bounds__(256) hmma_w1(
    float* __restrict__ C0, float* __restrict__ C1,
    const float* __restrict__ a_src1, const float* __restrict__ a_dst1,
    const float* __restrict__ a_feat,
    int M0, int M1, int tiles0) {
    SMEM_DECL
    const int tid = threadIdx.x;
    int t = blockIdx.y;
    const __nv_bfloat16 *Ah, *Al;
    float* C; int M, row0;
    bool is_n = (t < tiles0);
    if (is_n) { Ah = g_nadjh; Al = g_nadjl; C = C0; M = M0; row0 = t * 128; }
    else      { Ah = g_cadjh; Al = g_cadjl; C = C1; M = M1; row0 = (t - tiles0) * 128; }
    float acc[4][4][4] = {};
    HMMA_MAINLOOP3(Ah, Al, g_B1h, g_B1l, M, row0, 0, 256, 256, 16);
    EPI_VARS
    float av_[8], af_[8], ag_[8];
    const float* avec = is_n ? a_src1 : a_dst1;
#pragma unroll
    for (int ct = 0; ct < 4; ct++)
#pragma unroll
        for (int j = 0; j < 2; j++) {
            int c = wc * 32 + ct * 8 + q * 2 + j;
            av_[ct * 2 + j] = avec[c];
            af_[ct * 2 + j] = a_feat[c];
            ag_[ct * 2 + j] = a_feat[128 + c];
        }
#pragma unroll
    for (int rt = 0; rt < 4; rt++)
#pragma unroll
        for (int i = 0; i < 2; i++) {
            int er = row0 + wr * 64 + rt * 16 + g + i * 8;
            float s1 = 0.f, fs = 0.f, fd = 0.f;
            bool ok = (er < M);
            if (ok) {
                float* crow = C + (size_t)er * 128;
#pragma unroll
                for (int ct = 0; ct < 4; ct++) {
                    int c = wc * 32 + ct * 8 + q * 2;
                    float v0 = acc[rt][ct][i * 2 + 0], v1 = acc[rt][ct][i * 2 + 1];
                    *(float2*)(crow + c) = make_float2(v0, v1);
                    s1 += v0 * av_[ct * 2] + v1 * av_[ct * 2 + 1];
                    fs += v0 * af_[ct * 2] + v1 * af_[ct * 2 + 1];
                    fd += v0 * ag_[ct * 2] + v1 * ag_[ct * 2 + 1];
                }
            }
            s1 += __shfl_xor_sync(0xffffffffu, s1, 1);
            s1 += __shfl_xor_sync(0xffffffffu, s1, 2);
            fs += __shfl_xor_sync(0xffffffffu, fs, 1);
            fs += __shfl_xor_sync(0xffffffffu, fs, 2);
            fd += __shfl_xor_sync(0xffffffffu, fd, 1);
            fd += __shfl_xor_sync(0xffffffffu, fd, 2);
            if (ok && q == 0) {
                if (is_n) {
                    g_s1n[(size_t)er * 4 + wc] = s1;
                    atomicAdd(&g_fsn[er], fs);
                    atomicAdd(&g_fdn[er], fd);
                } else {
                    g_d1c[er * 4 + wc] = s1;
                    atomicAdd(&g_fsc[er], fs);
                    atomicAdd(&g_fdc[er], fd);
                }
            }
        }
}

// ====== HMMA GEMM: h2 = xc @ W2, fused s2/d2 scalar epilogue ==================
__global__ void __launch_bounds__(256) hmma_h2(
    float* __restrict__ C,
    const float* __restrict__ a_src2, const float* __restrict__ a_dst2) {
    SMEM_DECL
    const int tid = threadIdx.x;
    const int row0 = blockIdx.y * 128;
    float acc[4][4][4] = {};
    HMMA_MAINLOOP3(g_xch, g_xcl, g_B2h, g_B2l, BB, row0, 0, 128, 128, 8);
    EPI_VARS
    float av_[8], ad_[8];
#pragma unroll
    for (int ct = 0; ct < 4; ct++)
#pragma unroll
        for (int j = 0; j < 2; j++) {
            int c = wc * 32 + ct * 8 + q * 2 + j;
            av_[ct * 2 + j] = a_src2[c];
            ad_[ct * 2 + j] = a_dst2[c];
        }
#pragma unroll
    for (int rt = 0; rt < 4; rt++)
#pragma unroll
        for (int i = 0; i < 2; i++) {
            int er = row0 + wr * 64 + rt * 16 + g + i * 8;
            float* crow = C + (size_t)er * 128;
            float s = 0.f, d = 0.f;
#pragma unroll
            for (int ct = 0; ct < 4; ct++) {
                int c = wc * 32 + ct * 8 + q * 2;
                float v0 = acc[rt][ct][i * 2 + 0], v1 = acc[rt][ct][i * 2 + 1];
                *(float2*)(crow + c) = make_float2(v0, v1);
                s += v0 * av_[ct * 2] + v1 * av_[ct * 2 + 1];
                d += v0 * ad_[ct * 2] + v1 * ad_[ct * 2 + 1];
            }
            s += __shfl_xor_sync(0xffffffffu, s, 1);
            s += __shfl_xor_sync(0xffffffffu, s, 2);
            d += __shfl_xor_sync(0xffffffffu, d, 1);
            d += __shfl_xor_sync(0xffffffffu, d, 2);
            if (q == 0) {
                atomicAdd(&g_s2[er], s);
                atomicAdd(&g_d2[er], d);
            }
        }
}

// ---------------- stage A: cross-attention + n/cadj splits (R13 form) ---------
__global__ void __launch_bounds__(128) stageA(
    const float* __restrict__ cin, const float* __restrict__ nin,
    const float* __restrict__ counts_f, const int* __restrict__ offs,
    float* __restrict__ out_gate, float* __restrict__ out_nein) {
    int g = blockIdx.x;
    int tid = threadIdx.x, lane = tid & 31, warp = tid >> 5;
    int base = offs[g];
    int cnt = (int)(counts_f[g] + 0.5f);
    __shared__ float s_w[256];
    __shared__ float s_attn[32];
    s_w[tid] = g_w[(size_t)g * 256 + tid];
    s_w[tid + 128] = g_w[(size_t)g * 256 + 128 + tid];
    __syncthreads();
    for (int t = warp; t < cnt; t += 4) {
        const float* row = nin + (size_t)(base + t) * 256;
        float acc = 0.f;
#pragma unroll
        for (int i = 0; i < 8; i++) acc += row[lane + 32 * i] * s_w[lane + 32 * i];
        acc = warpsum(acc);
        if (!lane) s_attn[t] = acc * 0.08838834764831845f;
    }
    __syncthreads();
    if (tid == 0) {
        float m = -1e30f;
        for (int t = 0; t < cnt; t++) m = fmaxf(m, s_attn[t]);
        float s = 0.f;
        for (int t = 0; t < cnt; t++) { float e = __expf(s_attn[t] - m); s_attn[t] = e; s += e; }
        float inv = 1.f / (s + 1e-16f);
        for (int t = 0; t < cnt; t++) s_attn[t] *= inv;
    }
    __syncthreads();
    float acc0 = 0.f, acc1 = 0.f, sum0 = 0.f, sum1 = 0.f;
    for (int t = 0; t < cnt; t++) {
        size_t ro = (size_t)(base + t) * 256;
        const float* row = nin + ro;
        float v0 = row[tid], v1 = row[tid + 128];
        float a = s_attn[t];
        acc0 += a * v0; acc1 += a * v1;
        sum0 += v0;     sum1 += v1;
        __nv_bfloat16 nh0 = __float2bfloat16(v0);
        __nv_bfloat16 nh1 = __float2bfloat16(v1);
        g_nh[ro + tid] = nh0;           g_nh[ro + tid + 128] = nh1;
        g_nl[ro + tid] = __float2bfloat16(v0 - __bfloat162float(nh0));
        g_nl[ro + tid + 128] = __float2bfloat16(v1 - __bfloat162float(nh1));
    }
    float gate0 = ftanh(acc0), gate1 = ftanh(acc1);
    size_t o = (size_t)g * 256 + tid;
    float c0 = cin[o], c1 = cin[o + 128];
    out_gate[o] = gate0;            out_gate[o + 128] = gate1;
    float ca0 = c0 * gate0, ca1 = c1 * gate1;
    __nv_bfloat16 h0 = __float2bfloat16(ca0);
    __nv_bfloat16 h1 = __float2bfloat16(ca1);
    g_cadjh[o] = h0;                g_cadjh[o + 128] = h1;
    g_cadjl[o] = __float2bfloat16(ca0 - __bfloat162float(h0));
    g_cadjl[o + 128] = __float2bfloat16(ca1 - __bfloat162float(h1));
    out_nein[o] = c0 + sum0;        out_nein[o + 128] = c1 + sum1;
}

// ---------------- neighb_expr from bf16 splits (vectorized) -------------------
__global__ void __launch_bounds__(128) segmean_nadj(
    const float* __restrict__ counts_f, const int* __restrict__ offs,
    float* __restrict__ out_ne) {
    int g = blockIdx.x;
    int tid = threadIdx.x;          // handles cols 2*tid, 2*tid+1
    int base = offs[g];
    int cnt = (int)(counts_f[g] + 0.5f);
    float inv = 1.f / counts_f[g];
    float s0 = 0.f, s1 = 0.f;
    for (int t = 0; t < cnt; t++) {
        const uint32_t* ph = (const uint32_t*)(g_nadjh + (size_t)(base + t) * 256);
        const uint32_t* pl = (const uint32_t*)(g_nadjl + (size_t)(base + t) * 256);
        uint32_t hv = ph[tid], lv = pl[tid];
        s0 += bf16lo(hv) + bf16lo(lv);
        s1 += bf16hi(hv) + bf16hi(lv);
    }
    out_ne[(size_t)g * 256 + 2 * tid]     = s0 * inv;
    out_ne[(size_t)g * 256 + 2 * tid + 1] = s1 * inv;
}

// ---------------- GAT1 (R13 form, segmean separate) ---------------------------
__global__ void __launch_bounds__(128) gat1(
    const float* __restrict__ counts_f, const int* __restrict__ offs,
    const int* __restrict__ edges, int T, float* __restrict__ out_ew) {
    int g = blockIdx.x;
    int tid = threadIdx.x, lane = tid & 31, warp = tid >> 5;
    int base = offs[g];
    int cnt = (int)(counts_f[g] + 0.5f);
    int E2 = 2 * T;
    __shared__ float s_alpha[32][4];
    int head = warp;
    float d1 = g_d1c[g * 4 + head];
    float m = -1e30f;
    for (int t = lane; t < cnt; t += 32) {
        float e = lrelu02(g_s1n[(size_t)(base + t) * 4 + head] + d1);
        s_alpha[t][head] = e;
        m = fmaxf(m, e);
    }
    m = warpmax(m);
    float ssum = 0.f;
    for (int t = lane; t < cnt; t += 32) {
        float ex = __expf(s_alpha[t][head] - m);
        s_alpha[t][head] = ex;
        ssum += ex;
    }
    ssum = warpsum(ssum);
    float inv = 1.f / (ssum + 1e-16f);
    for (int t = lane; t < cnt; t += 32) s_alpha[t][head] *= inv;
    __syncthreads();
    int h4 = tid >> 5;
    float acc = 0.f;
    for (int t = 0; t < cnt; t++)
        acc += s_alpha[t][h4] * g_hn[(size_t)(base + t) * 128 + tid];
    size_t xo = (size_t)g * 128 + tid;
    g_xc[xo] = acc;
    __nv_bfloat16 xh = __float2bfloat16(acc);
    g_xch[xo] = xh;
    g_xcl[xo] = __float2bfloat16(acc - __bfloat162float(xh));
    if (tid < cnt) {
        int t = tid;
        int ei = base + t;
        float am = 0.25f * (s_alpha[t][0] + s_alpha[t][1] + s_alpha[t][2] + s_alpha[t][3]);
        float a2 = sigm(g_fsn[ei] + g_fdc[g]);
        float4 r1 = make_float4((float)edges[ei], (float)edges[E2 + ei], am, a2);
        *(float4*)(out_ew + (size_t)ei * 4) = r1;
        int ej = T + ei;
        float a2b = sigm(g_fsc[g] + g_fdn[ei]);
        float4 r2 = make_float4((float)edges[ej], (float)edges[E2 + ej], 1.0f, a2b);
        *(float4*)(out_ew + (size_t)ej * 4) = r2;
    }
}

// ---------------- VT graph softmax ----------------------------------------------
__global__ void vt_pass1(const int* __restrict__ evt) {
    int i = blockIdx.x * blockDim.x + threadIdx.x;
    if (i >= EVT) return;
    int sv = evt[i], dv = evt[EVT + i];
    float e = lrelu02(g_s2[sv] + g_d2[dv]);
    g_e2v[i] = e;
    atomicMaxFloat(&g_vmax[dv], e);
}
__global__ void vt_pass2(const int* __restrict__ evt) {
    int i = blockIdx.x * blockDim.x + threadIdx.x;
    if (i >= EVT) return;
    int dv = evt[EVT + i];
    float ex = __expf(g_e2v[i] - g_vmax[dv]);
    g_e2v[i] = ex;
    atomicAdd(&g_vsum[dv], ex);
}
__global__ void __launch_bounds__(128) vt_pass3(const int* __restrict__ evt,
                                                float* __restrict__ out_alpha,
                                                float* __restrict__ out_xn) {
    int i = blockIdx.x;
    int sv = evt[i], dv = evt[EVT + i];
    float alpha = g_e2v[i] / (g_vsum[dv] + 1e-16f);
    if (threadIdx.x == 0) out_alpha[i] = alpha;
    atomicAdd(&out_xn[(size_t)dv * 128 + threadIdx.x],
              alpha * g_h2[(size_t)sv * 128 + threadIdx.x]);
}

// ---------------- host launcher --------------------------------------------------
extern "C" void kernel_launch(void* const* d_in, const int* in_sizes, int n_in,
                              void* d_out, int out_size) {
    const float* c_in    = (const float*)d_in[0];
    const float* nb_in   = (const float*)d_in[1];
    const float* counts  = (const float*)d_in[2];
    const float* Wq_c    = (const float*)d_in[3];
    const float* Wk_c    = (const float*)d_in[4];
    const float* Wq_n    = (const float*)d_in[5];
    const float* Wk_n    = (const float*)d_in[6];
    const float* W1      = (const float*)d_in[7];
    const float* a_src1  = (const float*)d_in[8];
    const float* a_dst1  = (const float*)d_in[9];
    const float* a_feat  = (const float*)d_in[10];
    const float* W2      = (const float*)d_in[11];
    const float* a_src2  = (const float*)d_in[12];
    const float* a_dst2  = (const float*)d_in[13];
    const int*   seg     = (const int*)d_in[14];
    const int*   offs    = (const int*)d_in[17];
    const int*   edges   = (const int*)d_in[18];
    const int*   evt     = (const int*)d_in[19];
    int T = in_sizes[1] / GG;

    float* out = (float*)d_out;
    float* out_xn   = out;
    float* out_gate = out_xn + (size_t)BB * EMBD;
    float* out_attn = out_gate + (size_t)BB * GG;
    float* out_ne   = out_attn + (size_t)BB * GG;
    float* out_nein = out_ne + (size_t)BB * GG;
    float* out_ew   = out_nein + (size_t)BB * GG;
    float* out_avt  = out_ew + (size_t)8 * T;

    float *p_w, *p_ck, *p_hn, *p_hc, *p_h2;
    cudaGetSymbolAddress((void**)&p_w, g_w);
    cudaGetSymbolAddress((void**)&p_ck, g_ck);
    cudaGetSymbolAddress((void**)&p_hn, g_hn);
    cudaGetSymbolAddress((void**)&p_hc, g_hc);
    cudaGetSymbolAddress((void**)&p_h2, g_h2);

    static bool attr_done = false;
    if (!attr_done) {
        cudaFuncSetAttribute(hmma_wck, cudaFuncAttributeMaxDynamicSharedMemorySize, WCK_SMEM);
        attr_done = true;
    }

    int tilesT = (T + 127) / 128;

    prep_all<<<3008 + 4096, 256>>>(Wq_c, Wk_c, Wq_n, W1, W2, Wk_n,
                                   (const float4*)c_in, out_xn);

    hmma_wck<<<dim3(2, BB / 128), 256, WCK_SMEM>>>(p_w, p_ck);

    stageA<<<BB, 128>>>(c_in, nb_in, counts, offs, out_gate, out_nein);

    hmma_gate<<<dim3(2, tilesT), 256>>>(nb_in, p_ck, seg, offs, out_attn, T);
    segmean_nadj<<<BB, 128>>>(counts, offs, out_ne);

    hmma_w1<<<dim3(1, tilesT + BB / 128), 256>>>(p_hn, p_hc, a_src1, a_dst1,
                                                 a_feat, T, BB, tilesT);

    gat1<<<BB, 128>>>(counts, offs, edges, T, out_ew);

    hmma_h2<<<dim3(1, BB / 128), 256>>>(p_h2, a_src2, a_dst2);

    vt_pass1<<<(EVT + 255) / 256, 256>>>(evt);
    vt_pass2<<<(EVT + 255) / 256, 256>>>(evt);
    vt_pass3<<<EVT, 128>>>(evt, out_avt, out_xn);
}